// round 2
// baseline (speedup 1.0000x reference)
#include <cuda_runtime.h>

// ---------------- problem constants ----------------
#define MB    32          // batch
#define DCH   256         // channels
#define SSP   3136        // 56*56 spatial
#define NGRP  16          // groups
#define GS    16          // group size
#define NSAMP (MB*SSP)    // 100352 samples per channel
#define EPSV  1e-6f

#define QPI       (SSP/4)             // 784 quads (float4) per image per channel
#define QTOT      (MB*QPI)            // 25088 quads per group
#define STAT_BLKX 28                  // blocks per group (stats)
#define STAT_IT   (QTOT/(STAT_BLKX*16)) // 56 iterations (16 quad-slots/block)
#define WHT_BLKX  49                  // blocks per group (whiten)
#define WHT_IT    (QTOT/(WHT_BLKX*256)) // 2 iterations (256 quads/block/iter)

typedef unsigned long long ULL;

// ---------------- scratch ----------------
__device__ float  g_P[NGRP][GS][GS];      // raw product sums
__device__ float  g_S[NGRP][GS];          // raw channel sums
__device__ float2 g_W2[NGRP][GS][GS];     // whitening matrix packed (w,w)
__device__ float  g_bias[NGRP][GS];       // -W @ mu

// ---------------- f32x2 helpers ----------------
__device__ __forceinline__ ULL ffma2(ULL a, ULL b, ULL c) {
    ULL d;
    asm("fma.rn.f32x2 %0, %1, %2, %3;" : "=l"(d) : "l"(a), "l"(b), "l"(c));
    return d;
}
__device__ __forceinline__ ULL pack2(float lo, float hi) {
    ULL r;
    asm("mov.b64 %0, {%1, %2};" : "=l"(r) : "f"(lo), "f"(hi));
    return r;
}
__device__ __forceinline__ void unpack2(ULL v, float& lo, float& hi) {
    asm("mov.b64 {%0, %1}, %2;" : "=f"(lo), "=f"(hi) : "l"(v));
}

// ---------------- kernel 0: zero accumulators ----------------
__global__ void zero_kernel() {
    int tid = blockIdx.x * 256 + threadIdx.x;
    if (tid < NGRP * GS * GS) ((float*)g_P)[tid] = 0.0f;
    if (tid < NGRP * GS)      ((float*)g_S)[tid] = 0.0f;
}

// ---------------- kernel 1: stats, register-blocked, no smem staging ----------
// Block = 256 threads = 16 subtile positions (4x4 of the 16x16 matrix)
//                      x 16 quad slots. Thread accumulates a 4x4 subtile over
// 4-sample quads. Warp-level LDG dedup keeps DRAM traffic at 1x.
__global__ __launch_bounds__(256) void stats_kernel(const float* __restrict__ x) {
    __shared__ float sP[GS][GS];
    __shared__ float sS[GS];

    const int g   = blockIdx.y;
    const int tid = threadIdx.x;
    const int pos = tid & 15;
    const int ti  = pos >> 2;          // row subtile
    const int tj  = pos & 3;           // col subtile
    const int qs  = tid >> 4;          // quad slot 0..15

    if (tid < GS) sS[tid] = 0.0f;
    sP[tid >> 4][tid & 15] = 0.0f;
    __syncthreads();

    ULL acc[4][4];
#pragma unroll
    for (int r = 0; r < 4; r++)
#pragma unroll
        for (int c = 0; c < 4; c++) acc[r][c] = 0ull;
    ULL accs[4];
#pragma unroll
    for (int r = 0; r < 4; r++) accs[r] = 0ull;

    const ULL one2 = pack2(1.0f, 1.0f);
    const size_t cbase0 = (size_t)g * GS * SSP;   // + b*DCH*SSP

    for (int it = 0; it < STAT_IT; it++) {
        const int Q  = blockIdx.x * (STAT_IT * 16) + it * 16 + qs;
        const int b  = Q / QPI;
        const int qi = Q - b * QPI;
        const float* base = x + (size_t)b * DCH * SSP + cbase0 + 4 * qi;

        ULL xi[4][2], xj[4][2];
#pragma unroll
        for (int r = 0; r < 4; r++) {
            ulonglong2 v = *(const ulonglong2*)(base + (size_t)(ti * 4 + r) * SSP);
            xi[r][0] = v.x; xi[r][1] = v.y;
        }
#pragma unroll
        for (int c = 0; c < 4; c++) {
            ulonglong2 v = *(const ulonglong2*)(base + (size_t)(tj * 4 + c) * SSP);
            xj[c][0] = v.x; xj[c][1] = v.y;
        }
#pragma unroll
        for (int r = 0; r < 4; r++)
#pragma unroll
            for (int c = 0; c < 4; c++) {
                acc[r][c] = ffma2(xi[r][0], xj[c][0], acc[r][c]);
                acc[r][c] = ffma2(xi[r][1], xj[c][1], acc[r][c]);
            }
        if (tj == 0) {
#pragma unroll
            for (int r = 0; r < 4; r++) {
                accs[r] = ffma2(xi[r][0], one2, accs[r]);
                accs[r] = ffma2(xi[r][1], one2, accs[r]);
            }
        }
    }

    // reduce to shared, then one global atomic per entry per block
#pragma unroll
    for (int r = 0; r < 4; r++)
#pragma unroll
        for (int c = 0; c < 4; c++) {
            float lo, hi;
            unpack2(acc[r][c], lo, hi);
            atomicAdd(&sP[ti * 4 + r][tj * 4 + c], lo + hi);
        }
    if (tj == 0) {
#pragma unroll
        for (int r = 0; r < 4; r++) {
            float lo, hi;
            unpack2(accs[r], lo, hi);
            atomicAdd(&sS[ti * 4 + r], lo + hi);
        }
    }
    __syncthreads();

    atomicAdd(&g_P[g][tid >> 4][tid & 15], sP[tid >> 4][tid & 15]);
    if (tid < GS) atomicAdd(&g_S[g][tid], sS[tid]);
}

// ---------------- kernel 2: sigma -> Cholesky -> inv(T) (one warp/group) ------
__global__ void solve_kernel() {
    __shared__ float A[NGRP][GS][GS + 1];
    __shared__ float Wm[NGRP][GS][GS + 1];
    __shared__ float mu[NGRP][GS];

    const int g    = threadIdx.x >> 5;
    const int lane = threadIdx.x & 31;

    const float invn  = 1.0f / (float)NSAMP;
    const float scale = (1.0f - EPSV) / (float)(NSAMP - 1);

    if (lane < GS) mu[g][lane] = g_S[g][lane] * invn;
    __syncwarp();

    if (lane < GS) {
        const int j = lane;
        const float muj = mu[g][j];
        for (int i = 0; i < GS; i++) {
            float v = (g_P[g][i][j] - (float)NSAMP * mu[g][i] * muj) * scale;
            if (i == j) v += EPSV;
            A[g][i][j] = v;
        }
    }
    __syncwarp();

    for (int k = 0; k < GS; k++) {
        float s = 0.0f;
        if (lane < GS && lane >= k) {
            s = A[g][lane][k];
            for (int p = 0; p < k; p++) s -= A[g][lane][p] * A[g][k][p];
        }
        float d = __shfl_sync(0xffffffffu, s, k);
        d = sqrtf(d);
        if (lane < GS && lane >= k)
            A[g][lane][k] = (lane == k) ? d : s / d;
        __syncwarp();
    }

    if (lane < GS) {
        const int c = lane;
        for (int r = 0; r < GS; r++) Wm[g][r][c] = 0.0f;
        Wm[g][c][c] = 1.0f / A[g][c][c];
        for (int r = c + 1; r < GS; r++) {
            float t = 0.0f;
            for (int p = c; p < r; p++) t += A[g][r][p] * Wm[g][p][c];
            Wm[g][r][c] = -t / A[g][r][r];
        }
    }
    __syncwarp();

    if (lane < GS) {
        const int i = lane;
        float bias = 0.0f;
        for (int j = 0; j < GS; j++) {
            float w = Wm[g][i][j];
            bias -= w * mu[g][j];
            g_W2[g][i][j] = make_float2(w, w);
        }
        g_bias[g][i] = bias;
    }
}

// ---------------- kernel 3: whiten, register-resident inputs ------------------
// Thread = one 4-sample quad; loads all 16 group channels (16 LDG.128, fully
// coalesced), computes 16 outputs with W broadcast from smem, 16 STG.128.
__global__ __launch_bounds__(256) void whiten_kernel(const float* __restrict__ x,
                                                     float* __restrict__ out) {
    __shared__ float2 sW[GS][GS];
    __shared__ float  sB[GS];

    const int g   = blockIdx.y;
    const int tid = threadIdx.x;

    sW[tid >> 4][tid & 15] = g_W2[g][tid >> 4][tid & 15];
    if (tid < GS) sB[tid] = g_bias[g][tid];
    __syncthreads();

    const size_t cbase0 = (size_t)g * GS * SSP;

#pragma unroll
    for (int it = 0; it < WHT_IT; it++) {
        const int Q  = blockIdx.x * (WHT_IT * 256) + it * 256 + tid;
        const int b  = Q / QPI;
        const int qi = Q - b * QPI;
        const float* base  = x   + (size_t)b * DCH * SSP + cbase0 + 4 * qi;
        float*       obase = out + (size_t)b * DCH * SSP + cbase0 + 4 * qi;

        ULL in[2 * GS];
#pragma unroll
        for (int j = 0; j < GS; j++) {
            ulonglong2 v = *(const ulonglong2*)(base + (size_t)j * SSP);
            in[2 * j]     = v.x;
            in[2 * j + 1] = v.y;
        }

#pragma unroll
        for (int i = 0; i < GS; i++) {
            const float bi = sB[i];
            ULL a0 = pack2(bi, bi);
            ULL a1 = a0;
#pragma unroll
            for (int j = 0; j < GS; j++) {
                ULL w = *(const ULL*)&sW[i][j];   // broadcast
                a0 = ffma2(w, in[2 * j],     a0);
                a1 = ffma2(w, in[2 * j + 1], a1);
            }
            ulonglong2 o; o.x = a0; o.y = a1;
            *(ulonglong2*)(obase + (size_t)i * SSP) = o;
        }
    }
}

// ---------------- launch ----------------
extern "C" void kernel_launch(void* const* d_in, const int* in_sizes, int n_in,
                              void* d_out, int out_size) {
    const float* x = (const float*)d_in[0];
    float* out = (float*)d_out;

    zero_kernel<<<16, 256>>>();

    dim3 sgrid(STAT_BLKX, NGRP);           // 28 x 16 = 448 blocks
    stats_kernel<<<sgrid, 256>>>(x);

    solve_kernel<<<1, 512>>>();            // one warp per group

    dim3 wgrid(WHT_BLKX, NGRP);            // 49 x 16 = 784 blocks
    whiten_kernel<<<wgrid, 256>>>(x, out);
}

// round 4
// speedup vs baseline: 5.7320x; 5.7320x over previous
#include <cuda_runtime.h>

// ---------------- problem constants ----------------
#define MB    32          // batch
#define DCH   256         // channels
#define SSP   3136        // 56*56 spatial
#define NGRP  16          // groups
#define GS    16          // group size
#define NSAMP (MB*SSP)    // 100352 samples per channel
#define EPSV  1e-6f

// stats tiling: 64-sample tiles, 49 tiles per image, 1568 per group
#define STILE     64
#define TPI_S     (SSP/STILE)             // 49
#define STAT_BLKX 56                      // blocks per group
#define STAT_T    (MB*TPI_S/STAT_BLKX)    // 28 tiles per block
#define SPAD      66                      // padded row stride in floats

// whiten tiling: thread = 2-sample pair; 512 pairs per block (2 iters)
#define PPG       (NSAMP/2)               // 50176 pairs per group
#define WHT_BLKX  (PPG/512)               // 98 blocks per group
#define HSSP      (SSP/2)                 // 1568 pairs per image per channel

typedef unsigned long long ULL;

// ---------------- scratch ----------------
__device__ float  g_P[NGRP][GS][GS];      // raw product sums
__device__ float  g_S[NGRP][GS];          // raw channel sums
__device__ float2 g_W2[NGRP][GS][GS];     // whitening matrix packed (w,w)
__device__ float  g_bias[NGRP][GS];       // -W @ mu

// ---------------- f32x2 helpers ----------------
__device__ __forceinline__ ULL ffma2(ULL a, ULL b, ULL c) {
    ULL d;
    asm("fma.rn.f32x2 %0, %1, %2, %3;" : "=l"(d) : "l"(a), "l"(b), "l"(c));
    return d;
}
__device__ __forceinline__ ULL pack2(float lo, float hi) {
    ULL r;
    asm("mov.b64 %0, {%1, %2};" : "=l"(r) : "f"(lo), "f"(hi));
    return r;
}
__device__ __forceinline__ void unpack2(ULL v, float& lo, float& hi) {
    asm("mov.b64 {%0, %1}, %2;" : "=f"(lo), "=f"(hi) : "l"(v));
}

// ---------------- kernel 0: zero accumulators ----------------
__global__ void zero_kernel() {
    int tid = blockIdx.x * 256 + threadIdx.x;
    if (tid < NGRP * GS * GS) ((float*)g_P)[tid] = 0.0f;
    if (tid < NGRP * GS)      ((float*)g_S)[tid] = 0.0f;
}

// ---------------- kernel 1: stats, smem-staged + double-buffered --------------
// Block = 256 threads = 16 positions (4x4 subtile of 16x16) x 16 pair slots.
// Tile = 16 channels x 64 samples staged via coalesced float2 loads.
__global__ __launch_bounds__(256) void stats_kernel(const float* __restrict__ x) {
    __shared__ float sm[2][GS][SPAD];
    __shared__ float sP[GS][GS];
    __shared__ float sS[GS];

    const int g   = blockIdx.y;
    const int tid = threadIdx.x;
    const int pos = tid & 15;
    const int ti  = pos >> 2;
    const int tj  = pos & 3;
    const int qs  = tid >> 4;          // pair slot 0..15

    // staging coords: 512 float2 slots, thread covers rows srow and srow+8
    const int srow = tid >> 5;         // 0..7
    const int sc2  = tid & 31;         // float2 column 0..31

    if (tid < GS) sS[tid] = 0.0f;
    sP[tid >> 4][tid & 15] = 0.0f;

    ULL acc[4][4];
#pragma unroll
    for (int r = 0; r < 4; r++)
#pragma unroll
        for (int c = 0; c < 4; c++) acc[r][c] = 0ull;
    ULL accs[4];
#pragma unroll
    for (int r = 0; r < 4; r++) accs[r] = 0ull;
    const ULL one2 = pack2(1.0f, 1.0f);

    const size_t gbase = (size_t)g * GS * SSP;

    auto tile_off = [&](int tt) -> size_t {
        const int tileId = blockIdx.x * STAT_T + tt;
        const int b  = tileId / TPI_S;
        const int s0 = (tileId - b * TPI_S) * STILE;
        return (size_t)b * DCH * SSP + gbase + s0;
    };

    // prefetch tile 0
    size_t off = tile_off(0);
    float2 p0 = *(const float2*)(x + off + (size_t)srow * SSP + 2 * sc2);
    float2 p1 = *(const float2*)(x + off + (size_t)(srow + 8) * SSP + 2 * sc2);

    for (int tt = 0; tt < STAT_T; tt++) {
        const int buf = tt & 1;
        *(float2*)&sm[buf][srow][2 * sc2]     = p0;
        *(float2*)&sm[buf][srow + 8][2 * sc2] = p1;
        __syncthreads();

        if (tt + 1 < STAT_T) {
            size_t noff = tile_off(tt + 1);
            p0 = *(const float2*)(x + noff + (size_t)srow * SSP + 2 * sc2);
            p1 = *(const float2*)(x + noff + (size_t)(srow + 8) * SSP + 2 * sc2);
        }

        // compute: 2 pairs per slot (samples t = 2*(qs + 16*pp))
#pragma unroll
        for (int pp = 0; pp < 2; pp++) {
            const int t = 2 * (qs + 16 * pp);
            ULL xi[4], xj[4];
#pragma unroll
            for (int r = 0; r < 4; r++)
                xi[r] = *(const ULL*)&sm[buf][ti * 4 + r][t];
#pragma unroll
            for (int c = 0; c < 4; c++)
                xj[c] = *(const ULL*)&sm[buf][tj * 4 + c][t];
#pragma unroll
            for (int r = 0; r < 4; r++)
#pragma unroll
                for (int c = 0; c < 4; c++)
                    acc[r][c] = ffma2(xi[r], xj[c], acc[r][c]);
            if (tj == 0) {
#pragma unroll
                for (int r = 0; r < 4; r++)
                    accs[r] = ffma2(xi[r], one2, accs[r]);
            }
        }
        __syncthreads();
    }

    // reduce into shared, then one global atomic per entry per block
#pragma unroll
    for (int r = 0; r < 4; r++)
#pragma unroll
        for (int c = 0; c < 4; c++) {
            float lo, hi;
            unpack2(acc[r][c], lo, hi);
            atomicAdd(&sP[ti * 4 + r][tj * 4 + c], lo + hi);
        }
    if (tj == 0) {
#pragma unroll
        for (int r = 0; r < 4; r++) {
            float lo, hi;
            unpack2(accs[r], lo, hi);
            atomicAdd(&sS[ti * 4 + r], lo + hi);
        }
    }
    __syncthreads();

    atomicAdd(&g_P[g][tid >> 4][tid & 15], sP[tid >> 4][tid & 15]);
    if (tid < GS) atomicAdd(&g_S[g][tid], sS[tid]);
}

// ---------------- kernel 2: sigma -> Cholesky -> inv(T) (one warp/group) ------
__global__ void solve_kernel() {
    __shared__ float A[NGRP][GS][GS + 1];
    __shared__ float Wm[NGRP][GS][GS + 1];
    __shared__ float mu[NGRP][GS];

    const int g    = threadIdx.x >> 5;
    const int lane = threadIdx.x & 31;

    const float invn  = 1.0f / (float)NSAMP;
    const float scale = (1.0f - EPSV) / (float)(NSAMP - 1);

    if (lane < GS) mu[g][lane] = g_S[g][lane] * invn;
    __syncwarp();

    if (lane < GS) {
        const int j = lane;
        const float muj = mu[g][j];
        for (int i = 0; i < GS; i++) {
            float v = (g_P[g][i][j] - (float)NSAMP * mu[g][i] * muj) * scale;
            if (i == j) v += EPSV;
            A[g][i][j] = v;
        }
    }
    __syncwarp();

    for (int k = 0; k < GS; k++) {
        float s = 0.0f;
        if (lane < GS && lane >= k) {
            s = A[g][lane][k];
            for (int p = 0; p < k; p++) s -= A[g][lane][p] * A[g][k][p];
        }
        float d = __shfl_sync(0xffffffffu, s, k);
        d = sqrtf(d);
        if (lane < GS && lane >= k)
            A[g][lane][k] = (lane == k) ? d : s / d;
        __syncwarp();
    }

    if (lane < GS) {
        const int c = lane;
        for (int r = 0; r < GS; r++) Wm[g][r][c] = 0.0f;
        Wm[g][c][c] = 1.0f / A[g][c][c];
        for (int r = c + 1; r < GS; r++) {
            float t = 0.0f;
            for (int p = c; p < r; p++) t += A[g][r][p] * Wm[g][p][c];
            Wm[g][r][c] = -t / A[g][r][r];
        }
    }
    __syncwarp();

    if (lane < GS) {
        const int i = lane;
        float bias = 0.0f;
        for (int j = 0; j < GS; j++) {
            float w = Wm[g][i][j];
            bias -= w * mu[g][j];
            g_W2[g][i][j] = make_float2(w, w);
        }
        g_bias[g][i] = bias;
    }
}

// ---------------- kernel 3: whiten -------------------------------------------
// Thread = one 2-sample pair. Loads 16 channels as LDG.64 (warp: 256B fully
// coalesced), in[16] ULL stays registerized (proven footprint), W broadcast
// from smem, 16 independent ffma2 chains, 16 coalesced STG.64.
__global__ __launch_bounds__(256) void whiten_kernel(const float* __restrict__ x,
                                                     float* __restrict__ out) {
    __shared__ ULL   sW[GS][GS];
    __shared__ float sB[GS];

    const int g   = blockIdx.y;
    const int tid = threadIdx.x;

    {
        float2 w = g_W2[g][tid >> 4][tid & 15];
        sW[tid >> 4][tid & 15] = pack2(w.x, w.y);
        if (tid < GS) sB[tid] = g_bias[g][tid];
    }
    __syncthreads();

    const size_t gbase = (size_t)g * GS * SSP;

#pragma unroll
    for (int it = 0; it < 2; it++) {
        const int P  = blockIdx.x * 512 + it * 256 + tid;
        const int b  = P / HSSP;
        const int pr = P - b * HSSP;
        const float* base  = x   + (size_t)b * DCH * SSP + gbase + 2 * pr;
        float*       obase = out + (size_t)b * DCH * SSP + gbase + 2 * pr;

        ULL in[GS];
#pragma unroll
        for (int j = 0; j < GS; j++)
            in[j] = *(const ULL*)(base + (size_t)j * SSP);

#pragma unroll
        for (int i = 0; i < GS; i++) {
            const float bi = sB[i];
            ULL acc = pack2(bi, bi);
#pragma unroll
            for (int j = 0; j < GS; j++)
                acc = ffma2(sW[i][j], in[j], acc);
            *(ULL*)(obase + (size_t)i * SSP) = acc;
        }
    }
}

// ---------------- launch ----------------
extern "C" void kernel_launch(void* const* d_in, const int* in_sizes, int n_in,
                              void* d_out, int out_size) {
    const float* x = (const float*)d_in[0];
    float* out = (float*)d_out;

    zero_kernel<<<16, 256>>>();

    dim3 sgrid(STAT_BLKX, NGRP);           // 56 x 16 = 896 blocks
    stats_kernel<<<sgrid, 256>>>(x);

    solve_kernel<<<1, 512>>>();            // one warp per group

    dim3 wgrid(WHT_BLKX, NGRP);            // 98 x 16 = 1568 blocks
    whiten_kernel<<<wgrid, 256>>>(x, out);
}